// round 4
// baseline (speedup 1.0000x reference)
#include <cuda_runtime.h>
#include <math.h>

#define N_NODES 100000
#define N_EDGES 1600000
#define N_GRAPHS 512

// ---------------- device scratch (no cudaMalloc allowed) ----------------
// Vector-typed so the base addresses are hardware-guaranteed 16B-aligned.
__device__ float4   g_y1[N_NODES * 16];   // 64 ch per node
__device__ float4   g_z1[N_NODES * 16];
__device__ float4   g_y2[N_NODES * 8];    // 32 ch per node
__device__ float4   g_z2[N_NODES * 8];
__device__ int      g_indeg[N_NODES];
__device__ int      g_rowptr[N_NODES + 1];
__device__ int      g_cursor[N_NODES];
__device__ int      g_col[N_EDGES];
__device__ float    g_dinv[N_NODES];
__device__ float    g_bns[96];      // BN sums: [0,64) layer1, [64,96) layer2
__device__ float    g_bnq[96];      // BN sum of squares
__device__ float    g_scale[96];    // gamma * rstd
__device__ float    g_shift[96];    // beta - mean*scale
__device__ float    g_psum[N_GRAPHS * 32];
__device__ unsigned g_pmax[N_GRAPHS * 32];
__device__ float    g_cnt[N_GRAPHS];
__device__ int      g_bsums[128];
__device__ int      g_boff[128];

__device__ __forceinline__ float elu(float x) {
    return x > 0.f ? x : (__expf(x) - 1.f);
}
// monotonic float->uint encoding for atomicMax over signed floats
__device__ __forceinline__ unsigned encf(float f) {
    unsigned u = __float_as_uint(f);
    return (u & 0x80000000u) ? ~u : (u | 0x80000000u);
}
__device__ __forceinline__ float decf(unsigned u) {
    return (u & 0x80000000u) ? __uint_as_float(u ^ 0x80000000u)
                             : __uint_as_float(~u);
}

// ---------------- kernels ----------------
__global__ void k_zero() {
    int i = blockIdx.x * blockDim.x + threadIdx.x;
    if (i < N_NODES) g_indeg[i] = 0;
    if (i < N_GRAPHS * 32) { g_psum[i] = 0.f; g_pmax[i] = 0u; }
    if (i < N_GRAPHS) g_cnt[i] = 0.f;
    if (i < 96) { g_bns[i] = 0.f; g_bnq[i] = 0.f; }
}

__global__ void k_deg(const int* __restrict__ ei) {
    int e = blockIdx.x * blockDim.x + threadIdx.x;
    if (e < N_EDGES) atomicAdd(&g_indeg[ei[N_EDGES + e]], 1);
}

__global__ void k_scanA() {
    __shared__ int sd[1024];
    int i = blockIdx.x * 1024 + threadIdx.x;
    int v = (i < N_NODES) ? g_indeg[i] : 0;
    sd[threadIdx.x] = v;
    __syncthreads();
    for (int off = 1; off < 1024; off <<= 1) {
        int t = (threadIdx.x >= off) ? sd[threadIdx.x - off] : 0;
        __syncthreads();
        sd[threadIdx.x] += t;
        __syncthreads();
    }
    if (i < N_NODES) g_rowptr[i + 1] = sd[threadIdx.x];
    if (threadIdx.x == 1023) g_bsums[blockIdx.x] = sd[1023];
}

__global__ void k_scanB(int nb) {
    __shared__ int sd[128];
    int t = threadIdx.x;
    int v = (t < nb) ? g_bsums[t] : 0;
    sd[t] = v;
    __syncthreads();
    for (int off = 1; off < 128; off <<= 1) {
        int u = (t >= off) ? sd[t - off] : 0;
        __syncthreads();
        sd[t] += u;
        __syncthreads();
    }
    g_boff[t] = sd[t] - v;   // exclusive
}

__global__ void k_scanC() {
    int i = blockIdx.x * 1024 + threadIdx.x;
    if (i < N_NODES) {
        int off = g_boff[i >> 10];
        int inc = g_rowptr[i + 1] + off;
        g_rowptr[i + 1] = inc;
        int dg = g_indeg[i];
        g_cursor[i] = inc - dg;
        g_dinv[i] = rsqrtf((float)dg + 1.0f);
        if (i == 0) g_rowptr[0] = 0;
    }
}

__global__ void k_fill(const int* __restrict__ ei) {
    int e = blockIdx.x * blockDim.x + threadIdx.x;
    if (e < N_EDGES) {
        int s = ei[e];
        int d = ei[N_EDGES + e];
        int p = atomicAdd(&g_cursor[d], 1);
        g_col[p] = s;
    }
}

// y1 = (x @ W1) * dinv   (66 -> 64), 64x64 tile, 4x4 per thread
__global__ void k_gemm1(const float* __restrict__ x, const float* __restrict__ W1) {
    __shared__ float  xs[64][67];    // [row][k], padded (scalar access only)
    __shared__ float4 ws4[66][16];   // [k][col4]
    int tid = threadIdx.x;
    int row0 = blockIdx.x * 64;
    // W1 rows are 64 floats (16B multiple) and the buffer is cudaMalloc'd -> float4 ok
    const float4* __restrict__ W14 = (const float4*)W1;
    for (int i = tid; i < 66 * 16; i += 256) ws4[i >> 4][i & 15] = W14[i];
    for (int i = tid; i < 64 * 66; i += 256) {
        int r = i / 66, k = i - r * 66;
        int gr = row0 + r;
        xs[r][k] = (gr < N_NODES) ? x[gr * 66 + k] : 0.f;
    }
    __syncthreads();
    int tx = tid & 15, ty = tid >> 4;
    float acc[4][4];
    #pragma unroll
    for (int i = 0; i < 4; i++)
        #pragma unroll
        for (int j = 0; j < 4; j++) acc[i][j] = 0.f;
    for (int k = 0; k < 66; k++) {
        float4 wv = ws4[k][tx];
        #pragma unroll
        for (int i = 0; i < 4; i++) {
            float xv = xs[ty * 4 + i][k];
            acc[i][0] += xv * wv.x;
            acc[i][1] += xv * wv.y;
            acc[i][2] += xv * wv.z;
            acc[i][3] += xv * wv.w;
        }
    }
    #pragma unroll
    for (int i = 0; i < 4; i++) {
        int r = row0 + ty * 4 + i;
        if (r < N_NODES) {
            float d = g_dinv[r];
            g_y1[r * 16 + tx] = make_float4(acc[i][0] * d, acc[i][1] * d,
                                            acc[i][2] * d, acc[i][3] * d);
        }
    }
}

// layer-1 aggregation over CSR: z1[n] = dinv[n]*(y1[n] + sum y1[src]); fused BN stats
__global__ void k_agg64() {
    __shared__ float bs[64], bq[64];
    int tid = threadIdx.x;
    if (tid < 64) { bs[tid] = 0.f; bq[tid] = 0.f; }
    __syncthreads();
    int lane = tid & 31;
    int warp = blockIdx.x * (blockDim.x >> 5) + (tid >> 5);
    int nwarps = gridDim.x * (blockDim.x >> 5);
    const float2* __restrict__ y = (const float2*)g_y1;   // base 16B-aligned
    float2* __restrict__ z = (float2*)g_z1;
    float ls0 = 0.f, lq0 = 0.f, ls1 = 0.f, lq1 = 0.f;
    for (int n = warp; n < N_NODES; n += nwarps) {
        int start = g_rowptr[n], end = g_rowptr[n + 1];
        float2 a = y[n * 32 + lane];           // self term
        for (int base = start; base < end; base += 32) {
            int m = end - base;
            if (m > 32) m = 32;
            int s = (lane < m) ? g_col[base + lane] : 0;
            int j = 0;
            for (; j + 1 < m; j += 2) {
                int s0 = __shfl_sync(0xffffffffu, s, j);
                int s1 = __shfl_sync(0xffffffffu, s, j + 1);
                float2 v0 = y[s0 * 32 + lane];
                float2 v1 = y[s1 * 32 + lane];
                a.x += v0.x; a.y += v0.y;
                a.x += v1.x; a.y += v1.y;
            }
            if (j < m) {
                int s0 = __shfl_sync(0xffffffffu, s, j);
                float2 v0 = y[s0 * 32 + lane];
                a.x += v0.x; a.y += v0.y;
            }
        }
        float d = g_dinv[n];
        a.x *= d; a.y *= d;
        z[n * 32 + lane] = a;
        ls0 += a.x; lq0 += a.x * a.x;
        ls1 += a.y; lq1 += a.y * a.y;
    }
    atomicAdd(&bs[2 * lane], ls0);     atomicAdd(&bq[2 * lane], lq0);
    atomicAdd(&bs[2 * lane + 1], ls1); atomicAdd(&bq[2 * lane + 1], lq1);
    __syncthreads();
    if (tid < 64) { atomicAdd(&g_bns[tid], bs[tid]); atomicAdd(&g_bnq[tid], bq[tid]); }
}

__global__ void k_bnfin(const float* __restrict__ gamma,
                        const float* __restrict__ beta, int off, int C) {
    int c = threadIdx.x;
    if (c < C) {
        float m = g_bns[off + c] * (1.0f / N_NODES);
        float var = g_bnq[off + c] * (1.0f / N_NODES) - m * m;
        float r = rsqrtf(var + 1e-5f);
        float sc = gamma[c] * r;
        g_scale[off + c] = sc;
        g_shift[off + c] = beta[c] - m * sc;
    }
}

// h1 = elu(BN(z1)); y2 = (h1 @ W2) * dinv   (64 -> 32), 64x32 tile
__global__ void k_gemm2(const float* __restrict__ W2) {
    __shared__ float  hs[64][65];   // [row][k], padded (scalar access only)
    __shared__ float4 ws4[64][8];   // [k][col4]
    __shared__ float  sc[64], sh[64];
    int tid = threadIdx.x;          // 128 threads
    int row0 = blockIdx.x * 64;
    if (tid < 64) { sc[tid] = g_scale[tid]; sh[tid] = g_shift[tid]; }
    const float4* __restrict__ W24 = (const float4*)W2;  // rows of 32 floats
    for (int i = tid; i < 64 * 8; i += 128) ws4[i >> 3][i & 7] = W24[i];
    __syncthreads();
    const float* __restrict__ z1f = (const float*)g_z1;
    for (int i = tid; i < 64 * 64; i += 128) {
        int r = i >> 6, c = i & 63;
        int gr = row0 + r;
        float zz = (gr < N_NODES) ? z1f[gr * 64 + c] : 0.f;
        hs[r][c] = elu(zz * sc[c] + sh[c]);
    }
    __syncthreads();
    int tx = tid & 7, ty = tid >> 3;
    float acc[4][4];
    #pragma unroll
    for (int i = 0; i < 4; i++)
        #pragma unroll
        for (int j = 0; j < 4; j++) acc[i][j] = 0.f;
    for (int k = 0; k < 64; k++) {
        float4 wv = ws4[k][tx];
        #pragma unroll
        for (int i = 0; i < 4; i++) {
            float xv = hs[ty * 4 + i][k];
            acc[i][0] += xv * wv.x;
            acc[i][1] += xv * wv.y;
            acc[i][2] += xv * wv.z;
            acc[i][3] += xv * wv.w;
        }
    }
    #pragma unroll
    for (int i = 0; i < 4; i++) {
        int r = row0 + ty * 4 + i;
        if (r < N_NODES) {
            float d = g_dinv[r];
            g_y2[r * 8 + tx] = make_float4(acc[i][0] * d, acc[i][1] * d,
                                           acc[i][2] * d, acc[i][3] * d);
        }
    }
}

// layer-2 aggregation (32 channels, one float per lane)
__global__ void k_agg32() {
    __shared__ float bs[32], bq[32];
    int tid = threadIdx.x;
    if (tid < 32) { bs[tid] = 0.f; bq[tid] = 0.f; }
    __syncthreads();
    int lane = tid & 31;
    int warp = blockIdx.x * (blockDim.x >> 5) + (tid >> 5);
    int nwarps = gridDim.x * (blockDim.x >> 5);
    const float* __restrict__ y = (const float*)g_y2;
    float* __restrict__ z = (float*)g_z2;
    float ls = 0.f, lq = 0.f;
    for (int n = warp; n < N_NODES; n += nwarps) {
        int start = g_rowptr[n], end = g_rowptr[n + 1];
        float a = y[n * 32 + lane];
        for (int base = start; base < end; base += 32) {
            int m = end - base;
            if (m > 32) m = 32;
            int s = (lane < m) ? g_col[base + lane] : 0;
            int j = 0;
            for (; j + 1 < m; j += 2) {
                int s0 = __shfl_sync(0xffffffffu, s, j);
                int s1 = __shfl_sync(0xffffffffu, s, j + 1);
                float v0 = y[s0 * 32 + lane];
                float v1 = y[s1 * 32 + lane];
                a += v0; a += v1;
            }
            if (j < m) {
                int s0 = __shfl_sync(0xffffffffu, s, j);
                a += y[s0 * 32 + lane];
            }
        }
        float d = g_dinv[n];
        a *= d;
        z[n * 32 + lane] = a;
        ls += a; lq += a * a;
    }
    atomicAdd(&bs[lane], ls);
    atomicAdd(&bq[lane], lq);
    __syncthreads();
    if (tid < 32) { atomicAdd(&g_bns[64 + tid], bs[tid]); atomicAdd(&g_bnq[64 + tid], bq[tid]); }
}

// h2 = elu(BN(z2)); segment mean/max pooling (batch is sorted -> run-length local accum)
__global__ void k_pool(const int* __restrict__ batch) {
    int lane = threadIdx.x & 31;
    int warp = blockIdx.x * (blockDim.x >> 5) + (threadIdx.x >> 5);
    int n0 = warp * 32;
    if (n0 >= N_NODES) return;
    int n1 = n0 + 32;
    if (n1 > N_NODES) n1 = N_NODES;
    const float* __restrict__ z = (const float*)g_z2;
    float sc = g_scale[64 + lane], sh = g_shift[64 + lane];
    int cur = -1;
    float s = 0.f, mx = -3.0e38f;
    int cnt = 0;
    for (int n = n0; n < n1; n++) {
        int g = batch[n];
        float zz = z[n * 32 + lane];
        float h = elu(zz * sc + sh);
        if (g != cur) {
            if (cnt > 0) {
                atomicAdd(&g_psum[cur * 32 + lane], s);
                atomicMax(&g_pmax[cur * 32 + lane], encf(mx));
                if (lane == 0) atomicAdd(&g_cnt[cur], (float)cnt);
            }
            cur = g; s = 0.f; mx = -3.0e38f; cnt = 0;
        }
        s += h;
        mx = fmaxf(mx, h);
        cnt++;
    }
    if (cnt > 0) {
        atomicAdd(&g_psum[cur * 32 + lane], s);
        atomicMax(&g_pmax[cur * 32 + lane], encf(mx));
        if (lane == 0) atomicAdd(&g_cnt[cur], (float)cnt);
    }
}

// final MLP head: one warp per graph
__global__ void k_mlp(const float* __restrict__ Wm1, const float* __restrict__ bm1,
                      const float* __restrict__ Wm2, const float* __restrict__ bm2,
                      float* __restrict__ out) {
    __shared__ float gv[64], hid[32];
    int g = blockIdx.x, t = threadIdx.x;   // 32 threads
    float c = g_cnt[g];
    float cm = fmaxf(c, 1.f);
    gv[t] = g_psum[g * 32 + t] / cm;
    gv[32 + t] = (c > 0.f) ? decf(g_pmax[g * 32 + t]) : 0.f;
    __syncwarp();
    float acc = bm1[t];
    #pragma unroll
    for (int k = 0; k < 64; k++) acc += gv[k] * Wm1[k * 32 + t];
    hid[t] = elu(acc);
    __syncwarp();
    if (t < 2) {
        float o = bm2[t];
        #pragma unroll
        for (int k = 0; k < 32; k++) o += hid[k] * Wm2[k * 2 + t];
        out[g * 2 + t] = o;
    }
}

// ---------------- launch ----------------
extern "C" void kernel_launch(void* const* d_in, const int* in_sizes, int n_in,
                              void* d_out, int out_size) {
    const float* x     = (const float*)d_in[0];
    const int*   ei    = (const int*)d_in[1];     // int32! (JAX x64 disabled)
    // d_in[2] = edge_attr (unused by reference computation)
    const int*   batch = (const int*)d_in[3];     // int32!
    const float* W1    = (const float*)d_in[4];
    // b1 (d_in[5]) cancels inside batch norm
    const float* g1    = (const float*)d_in[6];
    const float* be1   = (const float*)d_in[7];
    const float* W2    = (const float*)d_in[8];
    // b2 (d_in[9]) cancels inside batch norm
    const float* g2    = (const float*)d_in[10];
    const float* be2   = (const float*)d_in[11];
    const float* Wm1   = (const float*)d_in[12];
    const float* bm1   = (const float*)d_in[13];
    const float* Wm2   = (const float*)d_in[14];
    const float* bm2   = (const float*)d_in[15];
    float* out = (float*)d_out;

    k_zero<<<391, 256>>>();
    k_deg<<<6250, 256>>>(ei);
    k_scanA<<<98, 1024>>>();
    k_scanB<<<1, 128>>>(98);
    k_scanC<<<98, 1024>>>();
    k_fill<<<6250, 256>>>(ei);
    k_gemm1<<<1563, 256>>>(x, W1);
    k_agg64<<<1480, 256>>>();
    k_bnfin<<<1, 64>>>(g1, be1, 0, 64);
    k_gemm2<<<1563, 128>>>(W2);
    k_agg32<<<1480, 256>>>();
    k_bnfin<<<1, 32>>>(g2, be2, 64, 32);
    k_pool<<<391, 256>>>(batch);
    k_mlp<<<512, 32>>>(Wm1, bm1, Wm2, bm2, out);
}

// round 5
// speedup vs baseline: 1.2051x; 1.2051x over previous
#include <cuda_runtime.h>
#include <math.h>

#define N_NODES 100000
#define N_EDGES 1600000
#define N_GRAPHS 512

// ---------------- device scratch (no cudaMalloc allowed) ----------------
__device__ float4   g_y1[N_NODES * 16];   // 64 ch per node
__device__ float4   g_z1[N_NODES * 16];
__device__ float4   g_y2[N_NODES * 8];    // 32 ch per node
__device__ float4   g_z2[N_NODES * 8];
__device__ int      g_indeg[N_NODES];
__device__ int      g_rowptr[N_NODES + 1];
__device__ int      g_cursor[N_NODES];
__device__ int      g_col[N_EDGES];
__device__ float    g_dinv[N_NODES];
__device__ float    g_bns[96];      // BN sums: [0,64) layer1, [64,96) layer2
__device__ float    g_bnq[96];      // BN sum of squares
__device__ float    g_psum[N_GRAPHS * 32];
__device__ unsigned g_pmax[N_GRAPHS * 32];
__device__ float    g_cnt[N_GRAPHS];
__device__ int      g_bsums[128];
__device__ int      g_boff[128];

__device__ __forceinline__ float elu(float x) {
    return x > 0.f ? x : (__expf(x) - 1.f);
}
__device__ __forceinline__ unsigned encf(float f) {
    unsigned u = __float_as_uint(f);
    return (u & 0x80000000u) ? ~u : (u | 0x80000000u);
}
__device__ __forceinline__ float decf(unsigned u) {
    return (u & 0x80000000u) ? __uint_as_float(u ^ 0x80000000u)
                             : __uint_as_float(~u);
}

// ---------------- kernels ----------------
__global__ void k_zero() {
    int i = blockIdx.x * blockDim.x + threadIdx.x;
    if (i < N_NODES) g_indeg[i] = 0;
    if (i < N_GRAPHS * 32) { g_psum[i] = 0.f; g_pmax[i] = 0u; }
    if (i < N_GRAPHS) g_cnt[i] = 0.f;
    if (i < 96) { g_bns[i] = 0.f; g_bnq[i] = 0.f; }
}

__global__ void k_deg(const int* __restrict__ ei) {
    int e = blockIdx.x * blockDim.x + threadIdx.x;
    if (e < N_EDGES) atomicAdd(&g_indeg[ei[N_EDGES + e]], 1);
}

__global__ void k_scanA() {
    __shared__ int sd[1024];
    int i = blockIdx.x * 1024 + threadIdx.x;
    int v = (i < N_NODES) ? g_indeg[i] : 0;
    sd[threadIdx.x] = v;
    __syncthreads();
    for (int off = 1; off < 1024; off <<= 1) {
        int t = (threadIdx.x >= off) ? sd[threadIdx.x - off] : 0;
        __syncthreads();
        sd[threadIdx.x] += t;
        __syncthreads();
    }
    if (i < N_NODES) g_rowptr[i + 1] = sd[threadIdx.x];
    if (threadIdx.x == 1023) g_bsums[blockIdx.x] = sd[1023];
}

__global__ void k_scanB(int nb) {
    __shared__ int sd[128];
    int t = threadIdx.x;
    int v = (t < nb) ? g_bsums[t] : 0;
    sd[t] = v;
    __syncthreads();
    for (int off = 1; off < 128; off <<= 1) {
        int u = (t >= off) ? sd[t - off] : 0;
        __syncthreads();
        sd[t] += u;
        __syncthreads();
    }
    g_boff[t] = sd[t] - v;   // exclusive
}

__global__ void k_scanC() {
    int i = blockIdx.x * 1024 + threadIdx.x;
    if (i < N_NODES) {
        int off = g_boff[i >> 10];
        int inc = g_rowptr[i + 1] + off;
        g_rowptr[i + 1] = inc;
        int dg = g_indeg[i];
        g_cursor[i] = inc - dg;
        g_dinv[i] = rsqrtf((float)dg + 1.0f);
        if (i == 0) g_rowptr[0] = 0;
    }
}

__global__ void k_fill(const int* __restrict__ ei) {
    int e = blockIdx.x * blockDim.x + threadIdx.x;
    if (e < N_EDGES) {
        int s = ei[e];
        int d = ei[N_EDGES + e];
        int p = atomicAdd(&g_cursor[d], 1);
        g_col[p] = s;
    }
}

// y1 = (x @ W1) * dinv   (66 -> 64), 64x64 tile, 4x4 per thread
__global__ void k_gemm1(const float* __restrict__ x, const float* __restrict__ W1) {
    __shared__ float  xs[64][67];
    __shared__ float4 ws4[66][16];
    int tid = threadIdx.x;
    int row0 = blockIdx.x * 64;
    const float4* __restrict__ W14 = (const float4*)W1;
    for (int i = tid; i < 66 * 16; i += 256) ws4[i >> 4][i & 15] = W14[i];
    for (int i = tid; i < 64 * 66; i += 256) {
        int r = i / 66, k = i - r * 66;
        int gr = row0 + r;
        xs[r][k] = (gr < N_NODES) ? x[gr * 66 + k] : 0.f;
    }
    __syncthreads();
    int tx = tid & 15, ty = tid >> 4;
    float acc[4][4];
    #pragma unroll
    for (int i = 0; i < 4; i++)
        #pragma unroll
        for (int j = 0; j < 4; j++) acc[i][j] = 0.f;
    for (int k = 0; k < 66; k++) {
        float4 wv = ws4[k][tx];
        #pragma unroll
        for (int i = 0; i < 4; i++) {
            float xv = xs[ty * 4 + i][k];
            acc[i][0] += xv * wv.x;
            acc[i][1] += xv * wv.y;
            acc[i][2] += xv * wv.z;
            acc[i][3] += xv * wv.w;
        }
    }
    #pragma unroll
    for (int i = 0; i < 4; i++) {
        int r = row0 + ty * 4 + i;
        if (r < N_NODES) {
            float d = g_dinv[r];
            g_y1[r * 16 + tx] = make_float4(acc[i][0] * d, acc[i][1] * d,
                                            acc[i][2] * d, acc[i][3] * d);
        }
    }
}

// layer-1 aggregation over CSR, fused BN stats. Unroll-4 gathers for MLP.
__global__ void __launch_bounds__(256, 8) k_agg64() {
    __shared__ float bs[64], bq[64];
    int tid = threadIdx.x;
    if (tid < 64) { bs[tid] = 0.f; bq[tid] = 0.f; }
    __syncthreads();
    int lane = tid & 31;
    int warp = blockIdx.x * 8 + (tid >> 5);
    int nwarps = gridDim.x * 8;
    const float2* __restrict__ y = (const float2*)g_y1;
    float2* __restrict__ z = (float2*)g_z1;
    float ls0 = 0.f, lq0 = 0.f, ls1 = 0.f, lq1 = 0.f;
    for (int n = warp; n < N_NODES; n += nwarps) {
        int start = g_rowptr[n], end = g_rowptr[n + 1];
        float2 a = y[n * 32 + lane];           // self term
        for (int base = start; base < end; base += 32) {
            int m = end - base;
            if (m > 32) m = 32;
            int s = (lane < m) ? g_col[base + lane] : 0;
            int j = 0;
            for (; j + 3 < m; j += 4) {
                int s0 = __shfl_sync(0xffffffffu, s, j);
                int s1 = __shfl_sync(0xffffffffu, s, j + 1);
                int s2 = __shfl_sync(0xffffffffu, s, j + 2);
                int s3 = __shfl_sync(0xffffffffu, s, j + 3);
                float2 v0 = y[s0 * 32 + lane];
                float2 v1 = y[s1 * 32 + lane];
                float2 v2 = y[s2 * 32 + lane];
                float2 v3 = y[s3 * 32 + lane];
                a.x += v0.x + v1.x + v2.x + v3.x;
                a.y += v0.y + v1.y + v2.y + v3.y;
            }
            for (; j < m; j++) {
                int s0 = __shfl_sync(0xffffffffu, s, j);
                float2 v0 = y[s0 * 32 + lane];
                a.x += v0.x; a.y += v0.y;
            }
        }
        float d = g_dinv[n];
        a.x *= d; a.y *= d;
        z[n * 32 + lane] = a;
        ls0 += a.x; lq0 += a.x * a.x;
        ls1 += a.y; lq1 += a.y * a.y;
    }
    atomicAdd(&bs[2 * lane], ls0);     atomicAdd(&bq[2 * lane], lq0);
    atomicAdd(&bs[2 * lane + 1], ls1); atomicAdd(&bq[2 * lane + 1], lq1);
    __syncthreads();
    if (tid < 64) { atomicAdd(&g_bns[tid], bs[tid]); atomicAdd(&g_bnq[tid], bq[tid]); }
}

// h1 = elu(BN(z1)); y2 = (h1 @ W2) * dinv. BN finalize fused per-block.
__global__ void k_gemm2(const float* __restrict__ W2,
                        const float* __restrict__ g1, const float* __restrict__ be1) {
    __shared__ float  hs[64][65];
    __shared__ float4 ws4[64][8];
    __shared__ float  sc[64], sh[64];
    int tid = threadIdx.x;          // 128 threads
    int row0 = blockIdx.x * 64;
    if (tid < 64) {
        float m = g_bns[tid] * (1.0f / N_NODES);
        float var = g_bnq[tid] * (1.0f / N_NODES) - m * m;
        float r = rsqrtf(var + 1e-5f);
        float s = g1[tid] * r;
        sc[tid] = s;
        sh[tid] = be1[tid] - m * s;
    }
    const float4* __restrict__ W24 = (const float4*)W2;
    for (int i = tid; i < 64 * 8; i += 128) ws4[i >> 3][i & 7] = W24[i];
    __syncthreads();
    const float* __restrict__ z1f = (const float*)g_z1;
    for (int i = tid; i < 64 * 64; i += 128) {
        int r = i >> 6, c = i & 63;
        int gr = row0 + r;
        float zz = (gr < N_NODES) ? z1f[gr * 64 + c] : 0.f;
        hs[r][c] = elu(zz * sc[c] + sh[c]);
    }
    __syncthreads();
    int tx = tid & 7, ty = tid >> 3;
    float acc[4][4];
    #pragma unroll
    for (int i = 0; i < 4; i++)
        #pragma unroll
        for (int j = 0; j < 4; j++) acc[i][j] = 0.f;
    for (int k = 0; k < 64; k++) {
        float4 wv = ws4[k][tx];
        #pragma unroll
        for (int i = 0; i < 4; i++) {
            float xv = hs[ty * 4 + i][k];
            acc[i][0] += xv * wv.x;
            acc[i][1] += xv * wv.y;
            acc[i][2] += xv * wv.z;
            acc[i][3] += xv * wv.w;
        }
    }
    #pragma unroll
    for (int i = 0; i < 4; i++) {
        int r = row0 + ty * 4 + i;
        if (r < N_NODES) {
            float d = g_dinv[r];
            g_y2[r * 8 + tx] = make_float4(acc[i][0] * d, acc[i][1] * d,
                                           acc[i][2] * d, acc[i][3] * d);
        }
    }
}

// layer-2 aggregation (32 channels), unroll-4
__global__ void __launch_bounds__(256, 8) k_agg32() {
    __shared__ float bs[32], bq[32];
    int tid = threadIdx.x;
    if (tid < 32) { bs[tid] = 0.f; bq[tid] = 0.f; }
    __syncthreads();
    int lane = tid & 31;
    int warp = blockIdx.x * 8 + (tid >> 5);
    int nwarps = gridDim.x * 8;
    const float* __restrict__ y = (const float*)g_y2;
    float* __restrict__ z = (float*)g_z2;
    float ls = 0.f, lq = 0.f;
    for (int n = warp; n < N_NODES; n += nwarps) {
        int start = g_rowptr[n], end = g_rowptr[n + 1];
        float a = y[n * 32 + lane];
        for (int base = start; base < end; base += 32) {
            int m = end - base;
            if (m > 32) m = 32;
            int s = (lane < m) ? g_col[base + lane] : 0;
            int j = 0;
            for (; j + 3 < m; j += 4) {
                int s0 = __shfl_sync(0xffffffffu, s, j);
                int s1 = __shfl_sync(0xffffffffu, s, j + 1);
                int s2 = __shfl_sync(0xffffffffu, s, j + 2);
                int s3 = __shfl_sync(0xffffffffu, s, j + 3);
                float v0 = y[s0 * 32 + lane];
                float v1 = y[s1 * 32 + lane];
                float v2 = y[s2 * 32 + lane];
                float v3 = y[s3 * 32 + lane];
                a += v0 + v1 + v2 + v3;
            }
            for (; j < m; j++) {
                int s0 = __shfl_sync(0xffffffffu, s, j);
                a += y[s0 * 32 + lane];
            }
        }
        float d = g_dinv[n];
        a *= d;
        z[n * 32 + lane] = a;
        ls += a; lq += a * a;
    }
    atomicAdd(&bs[lane], ls);
    atomicAdd(&bq[lane], lq);
    __syncthreads();
    if (tid < 32) { atomicAdd(&g_bns[64 + tid], bs[tid]); atomicAdd(&g_bnq[64 + tid], bq[tid]); }
}

// h2 = elu(BN(z2)); segment pooling (sorted batch -> run-length). BN fused.
__global__ void k_pool(const int* __restrict__ batch,
                       const float* __restrict__ g2, const float* __restrict__ be2) {
    int lane = threadIdx.x & 31;
    int warp = blockIdx.x * (blockDim.x >> 5) + (threadIdx.x >> 5);
    int n0 = warp * 32;
    if (n0 >= N_NODES) return;
    int n1 = n0 + 32;
    if (n1 > N_NODES) n1 = N_NODES;
    const float* __restrict__ z = (const float*)g_z2;
    float m = g_bns[64 + lane] * (1.0f / N_NODES);
    float var = g_bnq[64 + lane] * (1.0f / N_NODES) - m * m;
    float r = rsqrtf(var + 1e-5f);
    float sc = g2[lane] * r;
    float sh = be2[lane] - m * sc;
    int cur = -1;
    float s = 0.f, mx = -3.0e38f;
    int cnt = 0;
    for (int n = n0; n < n1; n++) {
        int g = batch[n];
        float zz = z[n * 32 + lane];
        float h = elu(zz * sc + sh);
        if (g != cur) {
            if (cnt > 0) {
                atomicAdd(&g_psum[cur * 32 + lane], s);
                atomicMax(&g_pmax[cur * 32 + lane], encf(mx));
                if (lane == 0) atomicAdd(&g_cnt[cur], (float)cnt);
            }
            cur = g; s = 0.f; mx = -3.0e38f; cnt = 0;
        }
        s += h;
        mx = fmaxf(mx, h);
        cnt++;
    }
    if (cnt > 0) {
        atomicAdd(&g_psum[cur * 32 + lane], s);
        atomicMax(&g_pmax[cur * 32 + lane], encf(mx));
        if (lane == 0) atomicAdd(&g_cnt[cur], (float)cnt);
    }
}

// final MLP head: one warp per graph
__global__ void k_mlp(const float* __restrict__ Wm1, const float* __restrict__ bm1,
                      const float* __restrict__ Wm2, const float* __restrict__ bm2,
                      float* __restrict__ out) {
    __shared__ float gv[64], hid[32];
    int g = blockIdx.x, t = threadIdx.x;   // 32 threads
    float c = g_cnt[g];
    float cm = fmaxf(c, 1.f);
    gv[t] = g_psum[g * 32 + t] / cm;
    gv[32 + t] = (c > 0.f) ? decf(g_pmax[g * 32 + t]) : 0.f;
    __syncwarp();
    float acc = bm1[t];
    #pragma unroll
    for (int k = 0; k < 64; k++) acc += gv[k] * Wm1[k * 32 + t];
    hid[t] = elu(acc);
    __syncwarp();
    if (t < 2) {
        float o = bm2[t];
        #pragma unroll
        for (int k = 0; k < 32; k++) o += hid[k] * Wm2[k * 2 + t];
        out[g * 2 + t] = o;
    }
}

// ---------------- launch ----------------
static cudaStream_t s_side = 0;
static cudaEvent_t  ev_fork = 0, ev_join = 0;

extern "C" void kernel_launch(void* const* d_in, const int* in_sizes, int n_in,
                              void* d_out, int out_size) {
    const float* x     = (const float*)d_in[0];
    const int*   ei    = (const int*)d_in[1];     // int32 (JAX x64 disabled)
    const int*   batch = (const int*)d_in[3];     // int32
    const float* W1    = (const float*)d_in[4];
    const float* g1    = (const float*)d_in[6];
    const float* be1   = (const float*)d_in[7];
    const float* W2    = (const float*)d_in[8];
    const float* g2    = (const float*)d_in[10];
    const float* be2   = (const float*)d_in[11];
    const float* Wm1   = (const float*)d_in[12];
    const float* bm1   = (const float*)d_in[13];
    const float* Wm2   = (const float*)d_in[14];
    const float* bm2   = (const float*)d_in[15];
    float* out = (float*)d_out;

    if (!s_side) {
        cudaStreamCreateWithFlags(&s_side, cudaStreamNonBlocking);
        cudaEventCreateWithFlags(&ev_fork, cudaEventDisableTiming);
        cudaEventCreateWithFlags(&ev_join, cudaEventDisableTiming);
    }

    k_zero<<<391, 256>>>();
    k_deg<<<6250, 256>>>(ei);
    k_scanA<<<98, 1024>>>();
    k_scanB<<<1, 128>>>(98);
    k_scanC<<<98, 1024>>>();
    // fork: gemm1 (needs only dinv) overlaps fill (needs only cursor)
    cudaEventRecord(ev_fork, 0);
    cudaStreamWaitEvent(s_side, ev_fork, 0);
    k_gemm1<<<1563, 256, 0, s_side>>>(x, W1);
    cudaEventRecord(ev_join, s_side);
    k_fill<<<6250, 256>>>(ei);
    cudaStreamWaitEvent(0, ev_join, 0);
    // join complete: aggregation needs both y1 and CSR
    k_agg64<<<1184, 256>>>();
    k_gemm2<<<1563, 128>>>(W2, g1, be1);
    k_agg32<<<1184, 256>>>();
    k_pool<<<391, 256>>>(batch, g2, be2);
    k_mlp<<<512, 32>>>(Wm1, bm1, Wm2, bm2, out);
}